// round 4
// baseline (speedup 1.0000x reference)
#include <cuda_runtime.h>
#include <cstdint>

// Attention: B=4, H=16, D=64, N=2048, layout (b,h,d,n), fp32.
// Flash-attention with warp-level TF32 mma.sync (m16n8k8), fp32 accumulate.
// CTA = 128 queries (8 warps x m16 rows), streams K/V in 64-key tiles.

#define DHEAD 64
#define SEQ   2048
#define BM    128
#define BN    64
#define SSTR  68      // smem row stride in 4B words (conflict-free for fragment access)
#define NWARP 8
#define SMEM_WORDS (DHEAD*SSTR*2 + NWARP*16*SSTR)   // Ks + Vs + Ps
#define SMEM_BYTES (SMEM_WORDS*4)

__device__ __forceinline__ uint32_t f2tf(float x) {
    uint32_t r;
    asm("cvt.rna.tf32.f32 %0, %1;" : "=r"(r) : "f"(x));
    return r;
}

__device__ __forceinline__ float ex2(float x) {
    float y;
    asm("ex2.approx.ftz.f32 %0, %1;" : "=f"(y) : "f"(x));
    return y;
}

__device__ __forceinline__ void mma_tf32(float c[4], const uint32_t a[4],
                                         uint32_t b0, uint32_t b1) {
    asm volatile(
        "mma.sync.aligned.m16n8k8.row.col.f32.tf32.tf32.f32 "
        "{%0,%1,%2,%3}, {%4,%5,%6,%7}, {%8,%9}, {%0,%1,%2,%3};"
        : "+f"(c[0]), "+f"(c[1]), "+f"(c[2]), "+f"(c[3])
        : "r"(a[0]), "r"(a[1]), "r"(a[2]), "r"(a[3]), "r"(b0), "r"(b1));
}

extern __shared__ uint32_t smem[];

__global__ __launch_bounds__(256)
void attn_tf32_kernel(const float* __restrict__ qg,
                      const float* __restrict__ kg,
                      const float* __restrict__ vg,
                      float* __restrict__ og) {
    uint32_t* Ks = smem;                         // [DHEAD][SSTR]  tf32 bits, K[d][j]
    uint32_t* Vs = Ks + DHEAD * SSTR;            // [DHEAD][SSTR]  tf32 bits, V[d][j]
    uint32_t* Ps = Vs + DHEAD * SSTR;            // [NWARP][16][SSTR] tf32 P

    const int bh = blockIdx.y;
    const size_t hoff = (size_t)bh * DHEAD * SEQ;
    const float* qh = qg + hoff;
    const float* kh = kg + hoff;
    const float* vh = vg + hoff;
    float*       oh = og + hoff;

    const int tid  = threadIdx.x;
    const int w    = tid >> 5;
    const int lane = tid & 31;
    const int g    = lane >> 2;   // group id (row within m16 half)
    const int tg   = lane & 3;    // thread-in-group

    const int i0 = blockIdx.x * BM + w * 16;   // this warp's query base

    // ---- Load Q fragments once (A operand, m16 x k64), scale folded in ----
    // scores in log2 domain: S = (q * D^-0.5 * log2(e))^T K
    const float QS = 0.125f * 1.4426950408889634f;
    uint32_t afrag[8][4];
#pragma unroll
    for (int kk = 0; kk < 8; kk++) {
        const int d0 = kk * 8;
        afrag[kk][0] = f2tf(qh[(size_t)(d0 + tg)     * SEQ + i0 + g    ] * QS);
        afrag[kk][1] = f2tf(qh[(size_t)(d0 + tg)     * SEQ + i0 + g + 8] * QS);
        afrag[kk][2] = f2tf(qh[(size_t)(d0 + tg + 4) * SEQ + i0 + g    ] * QS);
        afrag[kk][3] = f2tf(qh[(size_t)(d0 + tg + 4) * SEQ + i0 + g + 8] * QS);
    }

    float oacc[8][4];
#pragma unroll
    for (int nt = 0; nt < 8; nt++) {
        oacc[nt][0] = 0.f; oacc[nt][1] = 0.f; oacc[nt][2] = 0.f; oacc[nt][3] = 0.f;
    }
    float m0 = -1e30f, m1 = -1e30f;   // running row maxima (log2 domain)
    float l0 = 0.f,    l1 = 0.f;      // running row sums

    uint32_t* Pw = Ps + w * 16 * SSTR;

    for (int jt = 0; jt < SEQ / BN; jt++) {
        const int j0 = jt * BN;
        __syncthreads();   // all warps done reading previous K/V tile

        // ---- Load K,V tile (64 x 64 each) as tf32 bits, vectorized ----
#pragma unroll
        for (int t = 0; t < 4; t++) {
            const int idx = tid + t * 256;       // 0..1023 float4 slots
            const int d   = idx >> 4;
            const int j4  = (idx & 15) * 4;
            float4 kv = *reinterpret_cast<const float4*>(kh + (size_t)d * SEQ + j0 + j4);
            uint4 kb;
            kb.x = f2tf(kv.x); kb.y = f2tf(kv.y); kb.z = f2tf(kv.z); kb.w = f2tf(kv.w);
            *reinterpret_cast<uint4*>(Ks + d * SSTR + j4) = kb;
            float4 vv = *reinterpret_cast<const float4*>(vh + (size_t)d * SEQ + j0 + j4);
            uint4 vb;
            vb.x = f2tf(vv.x); vb.y = f2tf(vv.y); vb.z = f2tf(vv.z); vb.w = f2tf(vv.w);
            *reinterpret_cast<uint4*>(Vs + d * SSTR + j4) = vb;
        }
        __syncthreads();

        // ---- S = Q^T K  (m16 x n64, k=64) ----
        float sacc[8][4];
#pragma unroll
        for (int nt = 0; nt < 8; nt++) {
            sacc[nt][0] = 0.f; sacc[nt][1] = 0.f; sacc[nt][2] = 0.f; sacc[nt][3] = 0.f;
        }
#pragma unroll
        for (int kk = 0; kk < 8; kk++) {
#pragma unroll
            for (int nt = 0; nt < 8; nt++) {
                uint32_t b0 = Ks[(kk * 8 + tg)     * SSTR + nt * 8 + g];
                uint32_t b1 = Ks[(kk * 8 + tg + 4) * SSTR + nt * 8 + g];
                mma_tf32(sacc[nt], afrag[kk], b0, b1);
            }
        }

        // ---- Online softmax (rows g and g+8) ----
        float tm0 = -1e30f, tm1 = -1e30f;
#pragma unroll
        for (int nt = 0; nt < 8; nt++) {
            tm0 = fmaxf(tm0, fmaxf(sacc[nt][0], sacc[nt][1]));
            tm1 = fmaxf(tm1, fmaxf(sacc[nt][2], sacc[nt][3]));
        }
        tm0 = fmaxf(tm0, __shfl_xor_sync(0xffffffffu, tm0, 1));
        tm0 = fmaxf(tm0, __shfl_xor_sync(0xffffffffu, tm0, 2));
        tm1 = fmaxf(tm1, __shfl_xor_sync(0xffffffffu, tm1, 1));
        tm1 = fmaxf(tm1, __shfl_xor_sync(0xffffffffu, tm1, 2));

        const float nm0 = fmaxf(m0, tm0);
        const float nm1 = fmaxf(m1, tm1);
        const float a0 = ex2(m0 - nm0);
        const float a1 = ex2(m1 - nm1);

        float rs0 = 0.f, rs1 = 0.f;
#pragma unroll
        for (int nt = 0; nt < 8; nt++) {
            float p00 = ex2(sacc[nt][0] - nm0);
            float p01 = ex2(sacc[nt][1] - nm0);
            float p10 = ex2(sacc[nt][2] - nm1);
            float p11 = ex2(sacc[nt][3] - nm1);
            rs0 += p00 + p01;
            rs1 += p10 + p11;
            uint32_t* pr0 = Pw + g * SSTR + nt * 8 + 2 * tg;
            pr0[0] = f2tf(p00); pr0[1] = f2tf(p01);
            uint32_t* pr1 = Pw + (g + 8) * SSTR + nt * 8 + 2 * tg;
            pr1[0] = f2tf(p10); pr1[1] = f2tf(p11);
        }
        rs0 += __shfl_xor_sync(0xffffffffu, rs0, 1);
        rs0 += __shfl_xor_sync(0xffffffffu, rs0, 2);
        rs1 += __shfl_xor_sync(0xffffffffu, rs1, 1);
        rs1 += __shfl_xor_sync(0xffffffffu, rs1, 2);

        l0 = l0 * a0 + rs0;
        l1 = l1 * a1 + rs1;
        m0 = nm0;
        m1 = nm1;

#pragma unroll
        for (int nt = 0; nt < 8; nt++) {
            oacc[nt][0] *= a0; oacc[nt][1] *= a0;
            oacc[nt][2] *= a1; oacc[nt][3] *= a1;
        }

        __syncwarp();   // P tile visible to whole warp

        // ---- O += P V^T  (A = P m16 x k64, B[k=j][n=d] = V[d][j]) ----
#pragma unroll
        for (int kk = 0; kk < 8; kk++) {
            uint32_t pa[4];
            pa[0] = Pw[(g)     * SSTR + kk * 8 + tg];
            pa[1] = Pw[(g + 8) * SSTR + kk * 8 + tg];
            pa[2] = Pw[(g)     * SSTR + kk * 8 + tg + 4];
            pa[3] = Pw[(g + 8) * SSTR + kk * 8 + tg + 4];
#pragma unroll
            for (int nt = 0; nt < 8; nt++) {
                uint32_t b0 = Vs[(nt * 8 + g) * SSTR + kk * 8 + tg];
                uint32_t b1 = Vs[(nt * 8 + g) * SSTR + kk * 8 + tg + 4];
                mma_tf32(oacc[nt], pa, b0, b1);
            }
        }
    }

    // ---- Epilogue: normalize and store out[d][i] ----
    const float il0 = 1.f / l0;
    const float il1 = 1.f / l1;
#pragma unroll
    for (int nt = 0; nt < 8; nt++) {
        const int d = nt * 8 + 2 * tg;
        oh[(size_t)(d)     * SEQ + i0 + g]     = oacc[nt][0] * il0;
        oh[(size_t)(d + 1) * SEQ + i0 + g]     = oacc[nt][1] * il0;
        oh[(size_t)(d)     * SEQ + i0 + g + 8] = oacc[nt][2] * il1;
        oh[(size_t)(d + 1) * SEQ + i0 + g + 8] = oacc[nt][3] * il1;
    }
}

extern "C" void kernel_launch(void* const* d_in, const int* in_sizes, int n_in,
                              void* d_out, int out_size) {
    const float* q = (const float*)d_in[0];
    const float* k = (const float*)d_in[1];
    const float* v = (const float*)d_in[2];
    float* o = (float*)d_out;

    const int bh = in_sizes[0] / (DHEAD * SEQ);   // B*H = 64

    // Opt-in to >48KB dynamic smem (idempotent; safe under graph capture).
    cudaFuncSetAttribute(attn_tf32_kernel,
                         cudaFuncAttributeMaxDynamicSharedMemorySize, SMEM_BYTES);

    dim3 grid(SEQ / BM, bh);
    attn_tf32_kernel<<<grid, 256, SMEM_BYTES>>>(q, k, v, o);
}